// round 4
// baseline (speedup 1.0000x reference)
#include <cuda_runtime.h>
#include <cstdint>

// Problem constants (fixed by the reference: B=64, S=512, H=768)
#define PB 64
#define PS 512
#define PH 768
#define NTOK (PB * PS)                       // 32768 tokens
#define SPAN ((size_t)PB * PS * PS)          // 16,777,216 elements per output tensor

#define NBLK 128                             // persistent wave (<= SM count, co-resident)
#define NTOKBLK 64                           // producer blocks (half-batch each per round)

// Per-token scratch + pipeline flags (device globals: allocation-free)
__device__ float         g_a[NTOK];
__device__ float         g_c[NTOK];
__device__ unsigned char g_sc[NTOK];
__device__ unsigned char g_ec[NTOK];
__device__ int           g_done[PB];

// ---------------------------------------------------------------------------
__global__ void reset_kernel()
{
    if (threadIdx.x < PB) g_done[threadIdx.x] = 0;
}

// ---------------------------------------------------------------------------
// Span tile consumer: tile t = (batch b = t/8, 64 s-rows starting (t%8)*64).
// 1024 threads: 128 e-slices (4-wide, register-cached c/ec) x 8 row groups.
// Scratch reads via __ldcg (L2 = point of coherence across SMs).
// ---------------------------------------------------------------------------
__device__ __forceinline__ void span_tile(float* __restrict__ out, int t)
{
    const int b  = t >> 3;
    const int s0 = (t & 7) * 64;

    // Wait for batch b's token data (2 half-batch producers).
    if (threadIdx.x == 0) {
        while (atomicAdd(&g_done[b], 0) < 2) __nanosleep(200);
    }
    __syncthreads();

    const int e0   = (threadIdx.x & 127) << 2;
    const int rgrp = threadIdx.x >> 7;            // 0..7

    const float4 c4 = __ldcg(reinterpret_cast<const float4*>(g_c + (b << 9) + e0));
    const unsigned ecw = __ldcg(reinterpret_cast<const unsigned*>(g_ec + (b << 9) + e0));
    const float ec0 = (ecw & 0x000000FFu) ? 1.f : 0.f;
    const float ec1 = (ecw & 0x0000FF00u) ? 1.f : 0.f;
    const float ec2 = (ecw & 0x00FF0000u) ? 1.f : 0.f;
    const float ec3 = (ecw & 0xFF000000u) ? 1.f : 0.f;

    #pragma unroll
    for (int i = 0; i < 8; ++i) {
        const int s  = s0 + rgrp + 8 * i;
        const int bs = (b << 9) + s;
        const float a  = __ldcg(g_a + bs);
        const float sc = __ldcg(g_sc + bs) ? 1.f : 0.f;

        float4 sv;
        sv.x = a + c4.x;
        sv.y = a + c4.y;
        sv.z = a + c4.z;
        sv.w = a + c4.w;

        float4 mv;
        mv.x = (e0 + 0 >= s && sv.x > 0.f) ? sc * ec0 : 0.f;
        mv.y = (e0 + 1 >= s && sv.y > 0.f) ? sc * ec1 : 0.f;
        mv.z = (e0 + 2 >= s && sv.z > 0.f) ? sc * ec2 : 0.f;
        mv.w = (e0 + 3 >= s && sv.w > 0.f) ? sc * ec3 : 0.f;

        const size_t off = (size_t)bs * PS + e0;
        __stcs(reinterpret_cast<float4*>(out + off),        mv);   // span_mask
        __stcs(reinterpret_cast<float4*>(out + SPAN + off), sv);   // scores
    }
}

// ---------------------------------------------------------------------------
// Fused persistent kernel: 128 co-resident blocks.
//  Blocks 0..63  : token producers. Round r: batch b = 32r + blk/2, half = blk&1
//                  (256 tokens). Warp processes 2 tokens interleaved (shared
//                  smem weight reads, 12 outstanding LDG.128). Flags g_done[b].
//                  Afterwards: 2 span tiles each (batches 48..63).
//  Blocks 64..127: span consumers. 6 tiles each (batches 0..47), batch-ordered
//                  so they pipeline behind the producers' round structure.
// ---------------------------------------------------------------------------
__global__ void __launch_bounds__(1024, 1) fused_kernel(
    const float* __restrict__ rep,
    const int*   __restrict__ mask,
    const float* __restrict__ W_start,
    const float* __restrict__ b_start,
    const float* __restrict__ W_end,
    const float* __restrict__ b_end,
    const float* __restrict__ W_m,
    const float* __restrict__ b_m,
    float* __restrict__ out)
{
    const int blk = blockIdx.x;
    const int tid = threadIdx.x;

    if (blk < NTOKBLK) {
        // ---------------- token producer ----------------
        __shared__ float4 sw[4][PH / 4];   // 12 KB: 4 combined weight vectors

        for (int i = tid; i < PH; i += 1024) {
            reinterpret_cast<float*>(sw[0])[i] = W_start[i * 2 + 1] - W_start[i * 2 + 0];
            reinterpret_cast<float*>(sw[1])[i] = W_end[i * 2 + 1]   - W_end[i * 2 + 0];
            reinterpret_cast<float*>(sw[2])[i] = W_m[i];
            reinterpret_cast<float*>(sw[3])[i] = W_m[PH + i];
        }
        __syncthreads();

        const float bsd = b_start[1] - b_start[0];
        const float bed = b_end[1]   - b_end[0];
        const float bm  = b_m[0];

        const int wid  = tid >> 5;
        const int lane = tid & 31;
        const int half = blk & 1;

        for (int r = 0; r < 2; ++r) {
            const int b = r * 32 + (blk >> 1);
            const int base = b * PS + half * 256;

            #pragma unroll
            for (int j = 0; j < 4; ++j) {
                const int t0 = base + 2 * (wid + 32 * j);
                const int t1 = t0 + 1;
                const float4* r40 = reinterpret_cast<const float4*>(rep + (size_t)t0 * PH);
                const float4* r41 = reinterpret_cast<const float4*>(rep + (size_t)t1 * PH);

                float ds0 = 0.f, de0 = 0.f, va0 = 0.f, vc0 = 0.f;
                float ds1 = 0.f, de1 = 0.f, va1 = 0.f, vc1 = 0.f;
                #pragma unroll
                for (int k = 0; k < 6; ++k) {
                    const int i = lane + k * 32;
                    const float4 x0 = r40[i];
                    const float4 x1 = r41[i];
                    const float4 w0 = sw[0][i];
                    const float4 w1 = sw[1][i];
                    const float4 w2 = sw[2][i];
                    const float4 w3 = sw[3][i];
                    ds0 += x0.x * w0.x + x0.y * w0.y + x0.z * w0.z + x0.w * w0.w;
                    ds1 += x1.x * w0.x + x1.y * w0.y + x1.z * w0.z + x1.w * w0.w;
                    de0 += x0.x * w1.x + x0.y * w1.y + x0.z * w1.z + x0.w * w1.w;
                    de1 += x1.x * w1.x + x1.y * w1.y + x1.z * w1.z + x1.w * w1.w;
                    va0 += x0.x * w2.x + x0.y * w2.y + x0.z * w2.z + x0.w * w2.w;
                    va1 += x1.x * w2.x + x1.y * w2.y + x1.z * w2.z + x1.w * w2.w;
                    vc0 += x0.x * w3.x + x0.y * w3.y + x0.z * w3.z + x0.w * w3.w;
                    vc1 += x1.x * w3.x + x1.y * w3.y + x1.z * w3.z + x1.w * w3.w;
                }
                #pragma unroll
                for (int off = 16; off > 0; off >>= 1) {
                    ds0 += __shfl_down_sync(0xFFFFFFFFu, ds0, off);
                    ds1 += __shfl_down_sync(0xFFFFFFFFu, ds1, off);
                    de0 += __shfl_down_sync(0xFFFFFFFFu, de0, off);
                    de1 += __shfl_down_sync(0xFFFFFFFFu, de1, off);
                    va0 += __shfl_down_sync(0xFFFFFFFFu, va0, off);
                    va1 += __shfl_down_sync(0xFFFFFFFFu, va1, off);
                    vc0 += __shfl_down_sync(0xFFFFFFFFu, vc0, off);
                    vc1 += __shfl_down_sync(0xFFFFFFFFu, vc1, off);
                }
                if (lane == 0) {
                    const int v0 = (mask[t0] != 0);
                    const int v1 = (mask[t1] != 0);
                    g_sc[t0] = (unsigned char)(v0 && (ds0 + bsd >= 0.f));
                    g_sc[t1] = (unsigned char)(v1 && (ds1 + bsd >= 0.f));
                    g_ec[t0] = (unsigned char)(v0 && (de0 + bed >= 0.f));
                    g_ec[t1] = (unsigned char)(v1 && (de1 + bed >= 0.f));
                    g_a[t0]  = va0 + bm;
                    g_a[t1]  = va1 + bm;
                    g_c[t0]  = vc0;
                    g_c[t1]  = vc1;
                }
            }
            __syncthreads();
            if (tid == 0) {
                __threadfence();
                atomicAdd(&g_done[b], 1);
            }
            __syncthreads();
        }

        // Producers join span pool: tiles 384+blk, 448+blk (batches 48..63)
        span_tile(out, 384 + blk);
        span_tile(out, 448 + blk);
    } else {
        // ---------------- span consumer ----------------
        const int j = blk - NTOKBLK;           // 0..63
        #pragma unroll
        for (int i = 0; i < 6; ++i)
            span_tile(out, j + 64 * i);        // batches 0..47, batch-ordered
    }
}

// ---------------------------------------------------------------------------
extern "C" void kernel_launch(void* const* d_in, const int* in_sizes, int n_in,
                              void* d_out, int out_size)
{
    const float* rep     = (const float*)d_in[0];   // [B,S,H] fp32
    const int*   mask    = (const int*)  d_in[1];   // [B,S]  int32
    const float* W_start = (const float*)d_in[2];   // [H,2]
    const float* b_start = (const float*)d_in[3];   // [2]
    const float* W_end   = (const float*)d_in[4];   // [H,2]
    const float* b_end   = (const float*)d_in[5];   // [2]
    const float* W_m     = (const float*)d_in[6];   // [2H]
    const float* b_m     = (const float*)d_in[7];   // scalar
    float* out = (float*)d_out;                     // [mask | scores], each B*S*S fp32

    reset_kernel<<<1, PB>>>();
    fused_kernel<<<NBLK, 1024>>>(rep, mask, W_start, b_start, W_end, b_end,
                                 W_m, b_m, out);
}

// round 5
// speedup vs baseline: 1.4487x; 1.4487x over previous
#include <cuda_runtime.h>
#include <cstdint>

// Problem constants (fixed by the reference: B=64, S=512, H=768)
#define PB 64
#define PS 512
#define PH 768
#define NTOK (PB * PS)                       // 32768 tokens
#define SPAN ((size_t)PB * PS * PS)          // 16,777,216 elements per output tensor

// Per-token scratch (device globals: allocation-free, graph-capturable)
__device__ float         g_a[NTOK];
__device__ float         g_c[NTOK];
__device__ unsigned char g_sc[NTOK];
__device__ unsigned char g_ec[NTOK];

// ---------------------------------------------------------------------------
// Kernel 1: per-token fused matvecs, smem weights, 2 tokens per warp.
// Interleaving 2 tokens halves the smem weight traffic per token (12 LDS.128
// instead of 24) -- the R1 limiter -- and doubles LDG MLP (12 outstanding
// LDG.128 per warp). 512 threads/block, grid-stride so the 12 KB smem fill
// amortizes over 64 tokens per block.
// ---------------------------------------------------------------------------
__global__ void __launch_bounds__(512) token_kernel(
    const float* __restrict__ rep,
    const int*   __restrict__ mask,
    const float* __restrict__ W_start,
    const float* __restrict__ b_start,
    const float* __restrict__ W_end,
    const float* __restrict__ b_end,
    const float* __restrict__ W_m,
    const float* __restrict__ b_m)
{
    __shared__ float4 sw[4][PH / 4];   // 12 KB: 4 combined weight vectors

    const int tid = threadIdx.x;

    for (int i = tid; i < PH; i += 512) {
        reinterpret_cast<float*>(sw[0])[i] = W_start[i * 2 + 1] - W_start[i * 2 + 0];
        reinterpret_cast<float*>(sw[1])[i] = W_end[i * 2 + 1]   - W_end[i * 2 + 0];
        reinterpret_cast<float*>(sw[2])[i] = W_m[i];
        reinterpret_cast<float*>(sw[3])[i] = W_m[PH + i];
    }
    __syncthreads();

    const float bsd = b_start[1] - b_start[0];
    const float bed = b_end[1]   - b_end[0];
    const float bm  = b_m[0];

    const int warp = tid >> 5;          // 0..15
    const int lane = tid & 31;

    // Each block iteration covers 32 tokens (16 warps x 2 tokens).
    for (int base = blockIdx.x * 32; base < NTOK; base += gridDim.x * 32) {
        const int t0 = base + warp * 2;
        const int t1 = t0 + 1;
        const float4* r40 = reinterpret_cast<const float4*>(rep + (size_t)t0 * PH);
        const float4* r41 = reinterpret_cast<const float4*>(rep + (size_t)t1 * PH);

        float ds0 = 0.f, de0 = 0.f, va0 = 0.f, vc0 = 0.f;
        float ds1 = 0.f, de1 = 0.f, va1 = 0.f, vc1 = 0.f;
        #pragma unroll
        for (int k = 0; k < 6; ++k) {
            const int i = lane + k * 32;
            const float4 x0 = r40[i];
            const float4 x1 = r41[i];
            const float4 w0 = sw[0][i];
            const float4 w1 = sw[1][i];
            const float4 w2 = sw[2][i];
            const float4 w3 = sw[3][i];
            ds0 += x0.x * w0.x + x0.y * w0.y + x0.z * w0.z + x0.w * w0.w;
            ds1 += x1.x * w0.x + x1.y * w0.y + x1.z * w0.z + x1.w * w0.w;
            de0 += x0.x * w1.x + x0.y * w1.y + x0.z * w1.z + x0.w * w1.w;
            de1 += x1.x * w1.x + x1.y * w1.y + x1.z * w1.z + x1.w * w1.w;
            va0 += x0.x * w2.x + x0.y * w2.y + x0.z * w2.z + x0.w * w2.w;
            va1 += x1.x * w2.x + x1.y * w2.y + x1.z * w2.z + x1.w * w2.w;
            vc0 += x0.x * w3.x + x0.y * w3.y + x0.z * w3.z + x0.w * w3.w;
            vc1 += x1.x * w3.x + x1.y * w3.y + x1.z * w3.z + x1.w * w3.w;
        }
        #pragma unroll
        for (int off = 16; off > 0; off >>= 1) {
            ds0 += __shfl_down_sync(0xFFFFFFFFu, ds0, off);
            ds1 += __shfl_down_sync(0xFFFFFFFFu, ds1, off);
            de0 += __shfl_down_sync(0xFFFFFFFFu, de0, off);
            de1 += __shfl_down_sync(0xFFFFFFFFu, de1, off);
            va0 += __shfl_down_sync(0xFFFFFFFFu, va0, off);
            va1 += __shfl_down_sync(0xFFFFFFFFu, va1, off);
            vc0 += __shfl_down_sync(0xFFFFFFFFu, vc0, off);
            vc1 += __shfl_down_sync(0xFFFFFFFFu, vc1, off);
        }
        if (lane == 0) {
            const int v0 = (mask[t0] != 0);
            const int v1 = (mask[t1] != 0);
            g_sc[t0] = (unsigned char)(v0 && (ds0 + bsd >= 0.f));
            g_sc[t1] = (unsigned char)(v1 && (ds1 + bsd >= 0.f));
            g_ec[t0] = (unsigned char)(v0 && (de0 + bed >= 0.f));
            g_ec[t1] = (unsigned char)(v1 && (de1 + bed >= 0.f));
            g_a[t0]  = va0 + bm;
            g_a[t1]  = va1 + bm;
            g_c[t0]  = vc0;
            g_c[t1]  = vc1;
        }
    }
}

// ---------------------------------------------------------------------------
// Kernel 2 (R3's 22.4us version): span materialization, register-cached c-row
// + streaming stores. One block per (b, 16-row tile); each thread owns a fixed
// 4-wide e-slice reused across the 16 s-rows.
//   scores[b,s,e] = a[b,s] + c[b,e]
//   mask = start_cand[b,s] & end_cand[b,e] & (s<=e) & (score>0)
// ---------------------------------------------------------------------------
#define ROWS_PER_BLK 16
__global__ void __launch_bounds__(256) span_kernel(float* __restrict__ out)
{
    const int b    = blockIdx.x >> 5;                 // / (S/ROWS_PER_BLK) = /32
    const int s0   = (blockIdx.x & 31) * ROWS_PER_BLK;
    const int half = threadIdx.x >> 7;                // 0/1: which row of the pair
    const int e0   = (threadIdx.x & 127) << 2;        // fixed 4-wide e-slice

    const float4 c4  = *reinterpret_cast<const float4*>(g_c  + (b << 9) + e0);
    const uchar4 ec4 = *reinterpret_cast<const uchar4*>(g_ec + (b << 9) + e0);
    const float ecx = ec4.x ? 1.f : 0.f;
    const float ecy = ec4.y ? 1.f : 0.f;
    const float ecz = ec4.z ? 1.f : 0.f;
    const float ecw = ec4.w ? 1.f : 0.f;

    #pragma unroll
    for (int r = half; r < ROWS_PER_BLK; r += 2) {
        const int s  = s0 + r;
        const int bs = (b << 9) + s;
        const float a  = g_a[bs];
        const float sc = g_sc[bs] ? 1.f : 0.f;

        float4 sv;
        sv.x = a + c4.x;
        sv.y = a + c4.y;
        sv.z = a + c4.z;
        sv.w = a + c4.w;

        float4 mv;
        mv.x = (e0 + 0 >= s && sv.x > 0.f) ? sc * ecx : 0.f;
        mv.y = (e0 + 1 >= s && sv.y > 0.f) ? sc * ecy : 0.f;
        mv.z = (e0 + 2 >= s && sv.z > 0.f) ? sc * ecz : 0.f;
        mv.w = (e0 + 3 >= s && sv.w > 0.f) ? sc * ecw : 0.f;

        const size_t off = (size_t)bs * PS + e0;
        __stcs(reinterpret_cast<float4*>(out + off),        mv);   // span_mask
        __stcs(reinterpret_cast<float4*>(out + SPAN + off), sv);   // scores
    }
}

// ---------------------------------------------------------------------------
extern "C" void kernel_launch(void* const* d_in, const int* in_sizes, int n_in,
                              void* d_out, int out_size)
{
    const float* rep     = (const float*)d_in[0];   // [B,S,H] fp32
    const int*   mask    = (const int*)  d_in[1];   // [B,S]  int32
    const float* W_start = (const float*)d_in[2];   // [H,2]
    const float* b_start = (const float*)d_in[3];   // [2]
    const float* W_end   = (const float*)d_in[4];   // [H,2]
    const float* b_end   = (const float*)d_in[5];   // [2]
    const float* W_m     = (const float*)d_in[6];   // [2H]
    const float* b_m     = (const float*)d_in[7];   // scalar
    float* out = (float*)d_out;                     // [mask | scores], each B*S*S fp32

    // Kernel 1: 512 blocks x 512 threads; 32 tokens per block-iteration,
    // 2 grid-stride iterations (smem fill amortized over 64 tokens).
    token_kernel<<<512, 512>>>(rep, mask, W_start, b_start, W_end, b_end, W_m, b_m);

    // Kernel 2: 64 batches x 32 row-tiles = 2048 blocks x 256 threads.
    span_kernel<<<PB * (PS / ROWS_PER_BLK), 256>>>(out);
}

// round 6
// speedup vs baseline: 1.8000x; 1.2425x over previous
#include <cuda_runtime.h>
#include <cstdint>

// Problem constants (fixed by the reference: B=64, S=512, H=768)
#define PB 64
#define PS 512
#define PH 768
#define NTOK (PB * PS)                       // 32768 tokens
#define SPAN ((size_t)PB * PS * PS)          // 16,777,216 elements per output tensor

// Per-token scratch (device globals: allocation-free, graph-capturable)
__device__ float         g_a[NTOK];
__device__ float         g_c[NTOK];
__device__ unsigned char g_sc[NTOK];
__device__ unsigned char g_ec[NTOK];

// ---------------------------------------------------------------------------
// Kernel 1 (R1's measured-best version, verbatim): per-token fused matvecs.
// One warp per token, smem-resident combined weights, low register footprint
// (keeps occupancy high -- every variant that raised register pressure
// regressed). 6 x LDG.128 per token, 24 x LDS.128, 96 FFMA, shuffle reduce.
// ---------------------------------------------------------------------------
__global__ __launch_bounds__(256) void token_kernel(
    const float* __restrict__ rep,
    const int*   __restrict__ mask,
    const float* __restrict__ W_start,
    const float* __restrict__ b_start,
    const float* __restrict__ W_end,
    const float* __restrict__ b_end,
    const float* __restrict__ W_m,
    const float* __restrict__ b_m)
{
    __shared__ float4 sw[4][PH / 4];   // 12 KB: 4 combined weight vectors

    const int tid = threadIdx.x;

    // Stage combined weights into shared (once per block)
    for (int i = tid; i < PH; i += blockDim.x) {
        reinterpret_cast<float*>(sw[0])[i] = W_start[i * 2 + 1] - W_start[i * 2 + 0];
        reinterpret_cast<float*>(sw[1])[i] = W_end[i * 2 + 1]   - W_end[i * 2 + 0];
        reinterpret_cast<float*>(sw[2])[i] = W_m[i];
        reinterpret_cast<float*>(sw[3])[i] = W_m[PH + i];
    }
    __syncthreads();

    const int warp = tid >> 5;
    const int lane = tid & 31;
    const int token = blockIdx.x * (blockDim.x >> 5) + warp;
    if (token >= NTOK) return;

    const float4* r4 = reinterpret_cast<const float4*>(rep + (size_t)token * PH);

    float ds = 0.f, de = 0.f, va = 0.f, vc = 0.f;
    #pragma unroll
    for (int k = 0; k < PH / 4 / 32; ++k) {        // 6 iterations
        const int i = lane + k * 32;
        const float4 r  = r4[i];
        const float4 w0 = sw[0][i];
        const float4 w1 = sw[1][i];
        const float4 w2 = sw[2][i];
        const float4 w3 = sw[3][i];
        ds += r.x * w0.x + r.y * w0.y + r.z * w0.z + r.w * w0.w;
        de += r.x * w1.x + r.y * w1.y + r.z * w1.z + r.w * w1.w;
        va += r.x * w2.x + r.y * w2.y + r.z * w2.z + r.w * w2.w;
        vc += r.x * w3.x + r.y * w3.y + r.z * w3.z + r.w * w3.w;
    }
    #pragma unroll
    for (int off = 16; off > 0; off >>= 1) {
        ds += __shfl_down_sync(0xFFFFFFFFu, ds, off);
        de += __shfl_down_sync(0xFFFFFFFFu, de, off);
        va += __shfl_down_sync(0xFFFFFFFFu, va, off);
        vc += __shfl_down_sync(0xFFFFFFFFu, vc, off);
    }
    if (lane == 0) {
        const int valid = (mask[token] != 0);
        const float dsb = ds + (b_start[1] - b_start[0]);
        const float deb = de + (b_end[1]   - b_end[0]);
        g_sc[token] = (unsigned char)(valid && (dsb >= 0.f));
        g_ec[token] = (unsigned char)(valid && (deb >= 0.f));
        g_a[token]  = va + b_m[0];
        g_c[token]  = vc;
    }
}

// ---------------------------------------------------------------------------
// Kernel 2 (measured 22.4us twice, verbatim): span materialization with
// register-cached c-row + streaming stores. One block per (b, 16-row tile);
// each thread owns a fixed 4-wide e-slice reused across the 16 s-rows.
//   scores[b,s,e] = a[b,s] + c[b,e]
//   mask = start_cand[b,s] & end_cand[b,e] & (s<=e) & (score>0)
// ---------------------------------------------------------------------------
#define ROWS_PER_BLK 16
__global__ void __launch_bounds__(256) span_kernel(float* __restrict__ out)
{
    const int b    = blockIdx.x >> 5;                 // / (S/ROWS_PER_BLK) = /32
    const int s0   = (blockIdx.x & 31) * ROWS_PER_BLK;
    const int half = threadIdx.x >> 7;                // 0/1: which row of the pair
    const int e0   = (threadIdx.x & 127) << 2;        // fixed 4-wide e-slice

    const float4 c4  = *reinterpret_cast<const float4*>(g_c  + (b << 9) + e0);
    const uchar4 ec4 = *reinterpret_cast<const uchar4*>(g_ec + (b << 9) + e0);
    const float ecx = ec4.x ? 1.f : 0.f;
    const float ecy = ec4.y ? 1.f : 0.f;
    const float ecz = ec4.z ? 1.f : 0.f;
    const float ecw = ec4.w ? 1.f : 0.f;

    #pragma unroll
    for (int r = half; r < ROWS_PER_BLK; r += 2) {
        const int s  = s0 + r;
        const int bs = (b << 9) + s;
        const float a  = g_a[bs];
        const float sc = g_sc[bs] ? 1.f : 0.f;

        float4 sv;
        sv.x = a + c4.x;
        sv.y = a + c4.y;
        sv.z = a + c4.z;
        sv.w = a + c4.w;

        float4 mv;
        mv.x = (e0 + 0 >= s && sv.x > 0.f) ? sc * ecx : 0.f;
        mv.y = (e0 + 1 >= s && sv.y > 0.f) ? sc * ecy : 0.f;
        mv.z = (e0 + 2 >= s && sv.z > 0.f) ? sc * ecz : 0.f;
        mv.w = (e0 + 3 >= s && sv.w > 0.f) ? sc * ecw : 0.f;

        const size_t off = (size_t)bs * PS + e0;
        __stcs(reinterpret_cast<float4*>(out + off),        mv);   // span_mask
        __stcs(reinterpret_cast<float4*>(out + SPAN + off), sv);   // scores
    }
}

// ---------------------------------------------------------------------------
extern "C" void kernel_launch(void* const* d_in, const int* in_sizes, int n_in,
                              void* d_out, int out_size)
{
    const float* rep     = (const float*)d_in[0];   // [B,S,H] fp32
    const int*   mask    = (const int*)  d_in[1];   // [B,S]  int32
    const float* W_start = (const float*)d_in[2];   // [H,2]
    const float* b_start = (const float*)d_in[3];   // [2]
    const float* W_end   = (const float*)d_in[4];   // [H,2]
    const float* b_end   = (const float*)d_in[5];   // [2]
    const float* W_m     = (const float*)d_in[6];   // [2H]
    const float* b_m     = (const float*)d_in[7];   // scalar
    float* out = (float*)d_out;                     // [mask | scores], each B*S*S fp32

    // Kernel 1: 32768 tokens, 8 warps (tokens) per block -> 4096 blocks
    token_kernel<<<NTOK / 8, 256>>>(rep, mask, W_start, b_start, W_end, b_end, W_m, b_m);

    // Kernel 2: 64 batches x 32 row-tiles = 2048 blocks x 256 threads
    span_kernel<<<PB * (PS / ROWS_PER_BLK), 256>>>(out);
}